// round 14
// baseline (speedup 1.0000x reference)
#include <cuda_runtime.h>
#include <cuda_fp16.h>
#include <cuda_bf16.h>
#include <math.h>
#include <stdint.h>

// Problem constants (fixed by dataset)
#define NB   32
#define TMEL 2000
#define TPH  513
#define DIM  256
#define SPAD 520
#define KPAD 544    // padded phoneme axis for fp16 probs / phT

// fp32 buffers
static __device__ float g_bufA [NB * TMEL * DIM];
static __device__ float g_bufB [NB * TMEL * DIM];
static __device__ float g_ph0  [NB * TPH * DIM];
static __device__ float g_ph1  [NB * TPH * DIM];
static __device__ float g_dots [NB * TMEL * SPAD];
static __device__ float g_phsq [NB * TPH];
// fp16 weights + activation shadows
static __device__ __half g_hw   [8 * 512 * 768];
static __device__ __half g_hwf  [256 * 256];
static __device__ __half g_hmels[NB * TMEL * 80];
static __device__ __half g_hA   [NB * TMEL * DIM];
static __device__ __half g_hB   [NB * TMEL * DIM];
static __device__ __half g_hp0  [NB * TPH * DIM];
static __device__ __half g_hp1  [NB * TPH * DIM];
// fp16 attention operands
static __device__ __half g_probs[NB * TMEL * KPAD];
static __device__ __half g_phT  [NB * DIM * KPAD];

// ---------------------------------------------------------------------------
// Helpers
// ---------------------------------------------------------------------------
__device__ __forceinline__ uint32_t smem_u32(const void* p) {
    uint32_t a;
    asm("{ .reg .u64 t; cvta.to.shared.u64 t, %1; cvt.u32.u64 %0, t; }" : "=r"(a) : "l"(p));
    return a;
}
__device__ __forceinline__ void cp16(uint32_t dst, const void* src, uint32_t nbytes) {
    asm volatile("cp.async.ca.shared.global [%0], [%1], 16, %2;"
                 :: "r"(dst), "l"(src), "r"(nbytes) : "memory");
}
#define CP_COMMIT() asm volatile("cp.async.commit_group;" ::: "memory")
#define CP_WAIT1()  asm volatile("cp.async.wait_group 1;" ::: "memory")
#define CP_WAIT0()  asm volatile("cp.async.wait_group 0;" ::: "memory")

__device__ __forceinline__ void mma_f16(float* c, const uint32_t* a, uint32_t b0, uint32_t b1) {
    asm volatile(
        "mma.sync.aligned.m16n8k16.row.col.f32.f16.f16.f32 "
        "{%0,%1,%2,%3}, {%4,%5,%6,%7}, {%8,%9}, {%0,%1,%2,%3};"
        : "+f"(c[0]), "+f"(c[1]), "+f"(c[2]), "+f"(c[3])
        : "r"(a[0]), "r"(a[1]), "r"(a[2]), "r"(a[3]), "r"(b0), "r"(b1));
}
__device__ __forceinline__ void ldsm4(uint32_t* r, uint32_t addr) {
    asm volatile("ldmatrix.sync.aligned.m8n8.x4.shared.b16 {%0,%1,%2,%3}, [%4];"
                 : "=r"(r[0]), "=r"(r[1]), "=r"(r[2]), "=r"(r[3]) : "r"(addr));
}

// ---------------------------------------------------------------------------
// Weight packing
// ---------------------------------------------------------------------------
__global__ void pack_glu_w(const float* __restrict__ w, __half* __restrict__ wp) {
    int i = blockIdx.x * blockDim.x + threadIdx.x;
    if (i >= 4 * 512 * 768) return;
    int kk = i % 768;
    int r = i / 768;
    int o = r & 511;
    int blk = r >> 9;
    int tap = kk >> 8;
    int ci = kk & 255;
    wp[i] = __float2half_rn(w[(((size_t)blk * 512 + o) * 256 + ci) * 3 + tap]);
}

__global__ void pack_front_w(const float* __restrict__ w, __half* __restrict__ wp) {
    int i = blockIdx.x * blockDim.x + threadIdx.x;
    if (i >= 256 * 256) return;
    int kk = i & 255;
    int o = i >> 8;
    float v = 0.f;
    if (kk < 240) {
        int tap = kk / 80;
        int ci = kk - tap * 80;
        v = w[((size_t)o * 80 + ci) * 3 + tap];
    }
    wp[i] = __float2half_rn(v);
}

__global__ void f2h_kernel(const float* __restrict__ in, __half* __restrict__ out, int n4) {
    int i = blockIdx.x * blockDim.x + threadIdx.x;
    if (i >= n4) return;
    float4 v = *reinterpret_cast<const float4*>(in + i * 4);
    *reinterpret_cast<__half2*>(out + i * 4)     = __floats2half2_rn(v.x, v.y);
    *reinterpret_cast<__half2*>(out + i * 4 + 2) = __floats2half2_rn(v.z, v.w);
}

// ---------------------------------------------------------------------------
// Phoneme embedding (prepended blank 0) -> fp32 + fp16 shadow
// ---------------------------------------------------------------------------
__global__ void embed_kernel(const int* __restrict__ ph, const float* __restrict__ emb,
                             float* __restrict__ out, __half* __restrict__ hout) {
    int row = blockIdx.x;
    int b = row / TPH;
    int s = row - b * TPH;
    int tok = (s == 0) ? 0 : ph[b * 512 + (s - 1)];
    float4 v = *reinterpret_cast<const float4*>(emb + (size_t)tok * 256 + threadIdx.x * 4);
    *reinterpret_cast<float4*>(out + (size_t)row * 256 + threadIdx.x * 4) = v;
    *reinterpret_cast<__half2*>(hout + (size_t)row * 256 + threadIdx.x * 4)     = __floats2half2_rn(v.x, v.y);
    *reinterpret_cast<__half2*>(hout + (size_t)row * 256 + threadIdx.x * 4 + 2) = __floats2half2_rn(v.z, v.w);
}

// ---------------------------------------------------------------------------
// ph_enc fp16 transpose
// ---------------------------------------------------------------------------
__global__ void transpose_ph(const __half* __restrict__ hp, __half* __restrict__ phT) {
    int bd = blockIdx.x;
    int b = bd >> 8;
    int d = bd & 255;
    int s = threadIdx.x * 2;
    __half z = __float2half(0.f);
    __half v0 = (s     < TPH) ? hp[((size_t)b * TPH + s) * 256 + d]     : z;
    __half v1 = (s + 1 < TPH) ? hp[((size_t)b * TPH + s + 1) * 256 + d] : z;
    *reinterpret_cast<__half2*>(phT + ((size_t)b * 256 + d) * KPAD + s) = __halves2half2(v0, v1);
}

// ---------------------------------------------------------------------------
// Conv GEMM v2: 128 rows x (128+128) cols, fp16 mma + ldmatrix, K-chunk 64,
// 3-stage cp.async ring, fused GLU epilogue. 1 CTA/SM.
// Warps: 2(m: 64 rows) x 4(n: 32 cols per slab). acc[2][4][4][4] per thread.
// SMEM stage: A[128][72] + B[256][72] halves (pad 72 -> conflict-free ldmatrix).
// Dual-problem dispatch: blockIdx.x < tx0 -> P0 (mel), else P1 (ph).
// ---------------------------------------------------------------------------
#define LDH2  72
#define STAGE (384 * LDH2)           // halves per stage (128 A + 256 B rows)
#define BOFF2 (128 * LDH2)

struct ConvP {
    const __half* Ah; const float* Af; const __half* Bw; const float* bias;
    float* out; __half* hout; const int* lens; int lenoff; int T; int ldout;
};

template <int MODE>
__launch_bounds__(256, 1)
__global__ void conv_mma(ConvP p0, ConvP p1, int tx0)
{
    constexpr int CI = (MODE == 0) ? 256 : 80;
    constexpr int K  = (MODE == 0) ? 768 : 256;
    constexpr int NS = K / 64;

    extern __shared__ __half smh[];

    const int tid = threadIdx.x;
    const int b   = blockIdx.z;
    const bool is0 = (blockIdx.x < tx0);
    const ConvP P = is0 ? p0 : p1;
    const int t0  = (is0 ? blockIdx.x : blockIdx.x - tx0) * 128;
    const int n0  = blockIdx.y * 128;
    const int T   = P.T;

    const __half* Ahb = P.Ah + (size_t)b * T * CI;
    const int lim = (MODE == 0) ? (P.lens[b] + P.lenoff) : 0x7fffffff;

    // loader mapping: A row = tid>>1 (4 chunks), B row = tid (8 chunks)
    const int arow2 = tid >> 1;
    const int slab2 = tid >> 7;
    const int nloc2 = tid & 127;
    const int wrow  = (MODE == 0) ? (n0 + slab2 * 256 + nloc2) : (slab2 * 128 + nloc2);
    const __half* Brow = P.Bw + (size_t)wrow * K;

    const uint32_t smb = smem_u32(smh);

    auto loadStage = [&](int s) {
        const int st = s % 3;
        const int k0 = s * 64;
        // A (im2col 3-tap, masked via src-size 0)
        uint32_t adst = smb + (st * STAGE + arow2 * LDH2) * 2;
#pragma unroll
        for (int j = 0; j < 4; j++) {
            int hc = ((tid & 1) * 4 + j) * 8;
            int kk = k0 + hc;
            int tap = kk / CI;
            int ci = kk - tap * CI;
            int t = t0 + arow2 + tap - 1;
            bool ok = (t >= 0) && (t < T) && (t < lim);
            if (MODE == 1) ok = ok && (kk < 240);
            int tc = ok ? t : 0;
            cp16(adst + hc * 2, Ahb + (size_t)tc * CI + ci, ok ? 16u : 0u);
        }
        // B
        uint32_t bdst = smb + (st * STAGE + BOFF2 + tid * LDH2) * 2;
        const __half* bsrc = Brow + k0;
#pragma unroll
        for (int j = 0; j < 8; j++)
            cp16(bdst + j * 16, bsrc + j * 8, 16u);
        CP_COMMIT();
    };

    // mma thread mapping
    const int lane = tid & 31;
    const int g    = lane >> 2;
    const int tIg  = lane & 3;
    const int wm   = (tid >> 5) & 1;      // 2 m-warps
    const int wn   = (tid >> 5) >> 1;     // 4 n-warps

    // ldmatrix per-thread row/col bases
    const int arow = wm * 64 + (lane & 7) + ((lane >> 3) & 1) * 8;
    const int akc  = (lane >> 4) * 8;
    const int brow = wn * 32 + (lane & 7) + (lane >> 4) * 8;
    const int bkc  = ((lane >> 3) & 1) * 8;

    float acc[2][4][4][4];
#pragma unroll
    for (int s1 = 0; s1 < 2; s1++)
#pragma unroll
        for (int mt = 0; mt < 4; mt++)
#pragma unroll
            for (int nt = 0; nt < 4; nt++)
#pragma unroll
                for (int q = 0; q < 4; q++) acc[s1][mt][nt][q] = 0.f;

    loadStage(0);
    loadStage(1);

    for (int s = 0; s < NS; ++s) {
        if (s + 1 < NS) { CP_WAIT1(); } else { CP_WAIT0(); }
        __syncthreads();
        if (s + 2 < NS) loadStage(s + 2);

        const int st = s % 3;
        const uint32_t abase = smb + (st * STAGE + arow * LDH2 + akc) * 2;
        const uint32_t bbase = smb + (st * STAGE + BOFF2 + brow * LDH2 + bkc) * 2;
#pragma unroll
        for (int ks = 0; ks < 4; ks++) {
            uint32_t af[4][4];
#pragma unroll
            for (int mt = 0; mt < 4; mt++)
                ldsm4(af[mt], abase + (mt * 16 * LDH2 + ks * 16) * 2);
            uint32_t bf[2][2][4];
#pragma unroll
            for (int s1 = 0; s1 < 2; s1++)
#pragma unroll
                for (int ntp = 0; ntp < 2; ntp++)
                    ldsm4(bf[s1][ntp], bbase + ((s1 * 128 + ntp * 16) * LDH2 + ks * 16) * 2);
#pragma unroll
            for (int s1 = 0; s1 < 2; s1++)
#pragma unroll
                for (int ntp = 0; ntp < 2; ntp++)
#pragma unroll
                    for (int mt = 0; mt < 4; mt++) {
                        mma_f16(acc[s1][mt][2 * ntp],     af[mt], bf[s1][ntp][0], bf[s1][ntp][1]);
                        mma_f16(acc[s1][mt][2 * ntp + 1], af[mt], bf[s1][ntp][2], bf[s1][ntp][3]);
                    }
        }
    }

    const float SH = 0.70710678118654752440f;
    const float* Afb = P.Af + (size_t)b * T * 256;
#pragma unroll
    for (int mt = 0; mt < 4; mt++) {
#pragma unroll
        for (int h = 0; h < 2; h++) {
            const int t = t0 + wm * 64 + mt * 16 + g + 8 * h;
            if (t >= T) continue;
            if (MODE == 0) {
                const bool xon = (t < lim);
                const float* xr = Afb + (size_t)t * 256;
                float*  orow = P.out  + ((size_t)b * T + t) * P.ldout;
                __half* hrow = P.hout + ((size_t)b * T + t) * 256;
#pragma unroll
                for (int nt = 0; nt < 4; nt++) {
                    const int c = n0 + wn * 32 + nt * 8 + 2 * tIg;
                    float a0 = acc[0][mt][nt][2 * h + 0] + __ldg(P.bias + c + 0);
                    float a1 = acc[0][mt][nt][2 * h + 1] + __ldg(P.bias + c + 1);
                    float g0 = acc[1][mt][nt][2 * h + 0] + __ldg(P.bias + 256 + c + 0);
                    float g1 = acc[1][mt][nt][2 * h + 1] + __ldg(P.bias + 256 + c + 1);
                    float2 x = make_float2(0.f, 0.f);
                    if (xon) x = *reinterpret_cast<const float2*>(xr + c);
                    float2 o;
                    o.x = (a0 / (1.f + expf(-g0)) + x.x) * SH;
                    o.y = (a1 / (1.f + expf(-g1)) + x.y) * SH;
                    *reinterpret_cast<float2*>(orow + c) = o;
                    *reinterpret_cast<__half2*>(hrow + c) = __floats2half2_rn(o.x, o.y);
                }
            } else {
                float*  orow = P.out  + ((size_t)b * T + t) * P.ldout;
                __half* hrow = P.hout + ((size_t)b * T + t) * 256;
#pragma unroll
                for (int s1 = 0; s1 < 2; s1++) {
#pragma unroll
                    for (int nt = 0; nt < 4; nt++) {
                        const int c = s1 * 128 + wn * 32 + nt * 8 + 2 * tIg;
                        float2 o;
                        o.x = acc[s1][mt][nt][2 * h + 0] + __ldg(P.bias + c + 0);
                        o.y = acc[s1][mt][nt][2 * h + 1] + __ldg(P.bias + c + 1);
                        *reinterpret_cast<float2*>(orow + c) = o;
                        *reinterpret_cast<__half2*>(hrow + c) = __floats2half2_rn(o.x, o.y);
                    }
                }
            }
        }
    }
}

// ---------------------------------------------------------------------------
// fp16 attention GEMMs (proven R13 path, unchanged)
// ---------------------------------------------------------------------------
#define LDH 40
template <int EPI>
__launch_bounds__(256, 2)
__global__ void attn_mma(const __half* __restrict__ Ah, const __half* __restrict__ Bh,
                         const float* __restrict__ phsq, float* __restrict__ outp,
                         const int* __restrict__ lens, int lenoff, int T)
{
    constexpr int K  = (EPI == 0) ? 256 : KPAD;
    constexpr int NS = K / 32;
    constexpr int LDA = (EPI == 0) ? 256 : KPAD;
    constexpr int LDB = (EPI == 0) ? 256 : KPAD;
    constexpr int ASTAGE = 2 * 128 * LDH;
    constexpr int ABOFF  = 128 * LDH;

    extern __shared__ __half smh[];

    const int tid = threadIdx.x;
    const int b   = blockIdx.z;
    const int t0  = blockIdx.x * 128;
    const int n0  = blockIdx.y * 128;

    const __half* Ab = Ah + (size_t)b * T * LDA;
    const __half* Bb = Bh + (size_t)b * ((EPI == 0) ? TPH : 256) * LDB;

    const int lrow = tid >> 1;
    const int lhc  = (tid & 1) * 16;
    const uint32_t smb = smem_u32(smh);

    auto loadStage = [&](int s) {
        const int st = s % 3;
        const int k0 = s * 32;
        {
            int t = t0 + lrow;
            bool ok = (t < T);
            int tc = ok ? t : 0;
            uint32_t adst = smb + (st * ASTAGE + lrow * LDH + lhc) * 2;
            const __half* asrc = Ab + (size_t)tc * LDA + k0 + lhc;
#pragma unroll
            for (int j = 0; j < 2; j++)
                cp16(adst + j * 16, asrc + j * 8, ok ? 16u : 0u);
        }
        {
            int n = n0 + lrow;
            bool ok = (EPI == 1) || (n < TPH);
            int nc = ok ? n : 0;
            uint32_t bdst = smb + (st * ASTAGE + ABOFF + lrow * LDH + lhc) * 2;
            const __half* bsrc = Bb + (size_t)nc * LDB + k0 + lhc;
#pragma unroll
            for (int j = 0; j < 2; j++)
                cp16(bdst + j * 16, bsrc + j * 8, ok ? 16u : 0u);
        }
        CP_COMMIT();
    };

    const int lane = tid & 31;
    const int g    = lane >> 2;
    const int tIg  = lane & 3;
    const int wm   = (tid >> 5) & 3;
    const int wn   = (tid >> 5) >> 2;

    float acc[2][2][4][4];
#pragma unroll
    for (int s1 = 0; s1 < 2; s1++)
#pragma unroll
        for (int mt = 0; mt < 2; mt++)
#pragma unroll
            for (int nt = 0; nt < 4; nt++)
#pragma unroll
                for (int q = 0; q < 4; q++) acc[s1][mt][nt][q] = 0.f;

    loadStage(0);
    loadStage(1);

    for (int s = 0; s < NS; ++s) {
        if (s + 1 < NS) { CP_WAIT1(); } else { CP_WAIT0(); }
        __syncthreads();
        if (s + 2 < NS) loadStage(s + 2);

        const int st = s % 3;
        const __half* As = smh + st * ASTAGE;
        const __half* Bs = smh + st * ASTAGE + ABOFF;
#pragma unroll
        for (int ks = 0; ks < 2; ks++) {
            const int kb = ks * 16 + 2 * tIg;
            uint32_t af[2][4];
#pragma unroll
            for (int mt = 0; mt < 2; mt++) {
                const __half* ar = As + (wm * 32 + mt * 16 + g) * LDH;
                af[mt][0] = *reinterpret_cast<const uint32_t*>(ar + kb);
                af[mt][1] = *reinterpret_cast<const uint32_t*>(ar + 8 * LDH + kb);
                af[mt][2] = *reinterpret_cast<const uint32_t*>(ar + kb + 8);
                af[mt][3] = *reinterpret_cast<const uint32_t*>(ar + 8 * LDH + kb + 8);
            }
#pragma unroll
            for (int s1 = 0; s1 < 2; s1++) {
#pragma unroll
                for (int nt = 0; nt < 4; nt++) {
                    const __half* br = Bs + (s1 * 64 + wn * 32 + nt * 8 + g) * LDH;
                    uint32_t b0 = *reinterpret_cast<const uint32_t*>(br + kb);
                    uint32_t b1 = *reinterpret_cast<const uint32_t*>(br + kb + 8);
                    mma_f16(acc[s1][0][nt], af[0], b0, b1);
                    mma_f16(acc[s1][1][nt], af[1], b0, b1);
                }
            }
        }
    }

    const int lim = (EPI == 0) ? (lens[b] + lenoff) : 0;
#pragma unroll
    for (int mt = 0; mt < 2; mt++) {
#pragma unroll
        for (int h = 0; h < 2; h++) {
            const int t = t0 + wm * 32 + mt * 16 + g + 8 * h;
            if (t >= T) continue;
            if (EPI == 0) {
                float* crow = outp + ((size_t)b * T + t) * SPAD;
                const float* sqb = phsq + (size_t)b * TPH;
#pragma unroll
                for (int s1 = 0; s1 < 2; s1++) {
#pragma unroll
                    for (int nt = 0; nt < 4; nt++) {
#pragma unroll
                        for (int e = 0; e < 2; e++) {
                            const int s_ = n0 + s1 * 64 + wn * 32 + nt * 8 + 2 * tIg + e;
                            if (s_ < TPH) {
                                float vv = 2.f * acc[s1][mt][nt][2 * h + e] - sqb[s_];
                                if (s_ >= lim) vv = -1e9f;
                                crow[s_] = vv;
                            }
                        }
                    }
                }
            } else {
                float* crow = outp + ((size_t)b * T + t) * 512 + 256;
#pragma unroll
                for (int s1 = 0; s1 < 2; s1++) {
#pragma unroll
                    for (int nt = 0; nt < 4; nt++) {
                        const int c = n0 + s1 * 64 + wn * 32 + nt * 8 + 2 * tIg;
                        float2 o;
                        o.x = acc[s1][mt][nt][2 * h + 0];
                        o.y = acc[s1][mt][nt][2 * h + 1];
                        *reinterpret_cast<float2*>(crow + c) = o;
                    }
                }
            }
        }
    }
}

// ---------------------------------------------------------------------------
// ||ph_enc||^2 per row
// ---------------------------------------------------------------------------
__global__ void phsq_kernel(const float* __restrict__ ep, float* __restrict__ sq) {
    int row = blockIdx.x;
    int lane = threadIdx.x;
    const float* r = ep + (size_t)row * 256;
    float s = 0.f;
#pragma unroll
    for (int j = 0; j < 2; j++) {
        float4 v = *reinterpret_cast<const float4*>(r + lane * 4 + j * 128);
        s += v.x * v.x + v.y * v.y + v.z * v.z + v.w * v.w;
    }
#pragma unroll
    for (int o = 16; o; o >>= 1) s += __shfl_xor_sync(0xffffffffu, s, o);
    if (lane == 0) sq[row] = s;
}

// ---------------------------------------------------------------------------
// Row softmax over 513 fp32 logits -> fp16 probs (stride KPAD, pads zeroed)
// ---------------------------------------------------------------------------
__global__ void softmax_kernel(const float* __restrict__ dots, __half* __restrict__ probs) {
    size_t row = blockIdx.x;
    const float* p = dots + row * SPAD;
    __half* ph = probs + row * KPAD;
    int tid = threadIdx.x;
    int lane = tid & 31, wid = tid >> 5;
    __shared__ float red[32];

    float v[5];
    float mx = -3.0e38f;
#pragma unroll
    for (int j = 0; j < 5; j++) {
        int idx = tid + j * 128;
        v[j] = (idx < TPH) ? p[idx] : -3.0e38f;
        mx = fmaxf(mx, v[j]);
    }
#pragma unroll
    for (int o = 16; o; o >>= 1) mx = fmaxf(mx, __shfl_xor_sync(0xffffffffu, mx, o));
    if (lane == 0) red[wid] = mx;
    __syncthreads();
    if (tid < 32) {
        float m = (tid < 4) ? red[tid] : -3.0e38f;
#pragma unroll
        for (int o = 2; o; o >>= 1) m = fmaxf(m, __shfl_xor_sync(0xffffffffu, m, o));
        if (tid == 0) red[0] = m;
    }
    __syncthreads();
    mx = red[0];
    __syncthreads();

    float s = 0.f;
#pragma unroll
    for (int j = 0; j < 5; j++) {
        int idx = tid + j * 128;
        if (idx < TPH) { v[j] = expf(v[j] - mx); s += v[j]; }
    }
#pragma unroll
    for (int o = 16; o; o >>= 1) s += __shfl_xor_sync(0xffffffffu, s, o);
    if (lane == 0) red[wid] = s;
    __syncthreads();
    if (tid < 32) {
        float t2 = (tid < 4) ? red[tid] : 0.f;
#pragma unroll
        for (int o = 2; o; o >>= 1) t2 += __shfl_xor_sync(0xffffffffu, t2, o);
        if (tid == 0) red[0] = t2;
    }
    __syncthreads();
    float inv = 1.f / red[0];
#pragma unroll
    for (int j = 0; j < 5; j++) {
        int idx = tid + j * 128;
        if (idx < TPH) ph[idx] = __float2half_rn(v[j] * inv);
        else if (idx < KPAD) ph[idx] = __float2half(0.f);
    }
}

// ---------------------------------------------------------------------------
// Launcher
// ---------------------------------------------------------------------------
extern "C" void kernel_launch(void* const* d_in, const int* in_sizes, int n_in,
                              void* d_out, int out_size)
{
    const float* mels = (const float*)d_in[0];
    const int*   phon = (const int*)  d_in[1];
    const int*   mlen = (const int*)  d_in[2];
    const int*   plen = (const int*)  d_in[3];
    const float* emb  = (const float*)d_in[4];
    const float* mcw  = (const float*)d_in[5];
    const float* mcb  = (const float*)d_in[6];
    const float* phw  = (const float*)d_in[7];
    const float* phb  = (const float*)d_in[8];
    const float* melw = (const float*)d_in[9];
    const float* melb = (const float*)d_in[10];
    float* out = (float*)d_out;

    float *bufA, *bufB, *ph0, *ph1, *dots, *phsq;
    __half *hw, *hwf, *hmels, *hA, *hB, *hp0, *hp1, *probs, *phT;
    cudaGetSymbolAddress((void**)&bufA, g_bufA);
    cudaGetSymbolAddress((void**)&bufB, g_bufB);
    cudaGetSymbolAddress((void**)&ph0,  g_ph0);
    cudaGetSymbolAddress((void**)&ph1,  g_ph1);
    cudaGetSymbolAddress((void**)&dots, g_dots);
    cudaGetSymbolAddress((void**)&phsq, g_phsq);
    cudaGetSymbolAddress((void**)&hw,   g_hw);
    cudaGetSymbolAddress((void**)&hwf,  g_hwf);
    cudaGetSymbolAddress((void**)&hmels,g_hmels);
    cudaGetSymbolAddress((void**)&hA,   g_hA);
    cudaGetSymbolAddress((void**)&hB,   g_hB);
    cudaGetSymbolAddress((void**)&hp0,  g_hp0);
    cudaGetSymbolAddress((void**)&hp1,  g_hp1);
    cudaGetSymbolAddress((void**)&probs,g_probs);
    cudaGetSymbolAddress((void**)&phT,  g_phT);

    const int SMEMSZ2 = 3 * STAGE * 2;               // 165888 B (conv)
    const int SMEMSZA = 3 * 2 * 128 * LDH * 2;       // 61440 B (attn)
    cudaFuncSetAttribute(conv_mma<0>, cudaFuncAttributeMaxDynamicSharedMemorySize, SMEMSZ2);
    cudaFuncSetAttribute(conv_mma<1>, cudaFuncAttributeMaxDynamicSharedMemorySize, SMEMSZ2);
    cudaFuncSetAttribute(attn_mma<0>, cudaFuncAttributeMaxDynamicSharedMemorySize, SMEMSZA);
    cudaFuncSetAttribute(attn_mma<1>, cudaFuncAttributeMaxDynamicSharedMemorySize, SMEMSZA);

    // 1. pack weights; mels -> fp16
    pack_glu_w<<<(4 * 512 * 768 + 255) / 256, 256>>>(phw, hw);
    pack_glu_w<<<(4 * 512 * 768 + 255) / 256, 256>>>(melw, hw + (size_t)4 * 512 * 768);
    pack_front_w<<<(256 * 256 + 255) / 256, 256>>>(mcw, hwf);
    f2h_kernel<<<(NB * TMEL * 80 / 4 + 255) / 256, 256>>>(mels, hmels, NB * TMEL * 80 / 4);

    // 2. phoneme embedding
    embed_kernel<<<NB * TPH, 64>>>(phon, emb, ph0, hp0);

    const int MTX = (TMEL + 127) / 128;   // 16
    const int PTX = (TPH + 127) / 128;    // 5

    // 3. mel front conv -> bufA (+hA)
    {
        ConvP p0 = { hmels, nullptr, hwf, mcb, bufA, hA, nullptr, 0, TMEL, 256 };
        dim3 g(MTX, 1, NB);
        conv_mma<1><<<g, 256, SMEMSZ2>>>(p0, p0, MTX);
    }

    // 4+5. fused GLU layers: mel (tiles 0..15) + ph (tiles 16..20) per launch
    {
        float*  mpin = bufA;  float*  mpout = bufB;
        __half* mhin = hA;    __half* mhpo  = hB;
        float*  ppin = ph0;   float*  ppout = ph1;
        __half* phin = hp0;   __half* phpo  = hp1;
        dim3 g(MTX + PTX, 2, NB);
        for (int i = 0; i < 4; i++) {
            bool last = (i == 3);
            ConvP pm = { mhin, mpin, hw + (size_t)(4 + i) * 512 * 768, melb + i * 512,
                         last ? out : mpout, mhpo, mlen, 0, TMEL, last ? 512 : 256 };
            ConvP pp = { phin, ppin, hw + (size_t)i * 512 * 768, phb + i * 512,
                         ppout, phpo, plen, 1, TPH, 256 };
            conv_mma<0><<<g, 256, SMEMSZ2>>>(pm, pp, MTX);
            { float*  t = mpin; mpin = mpout; mpout = t; }
            { __half* t = mhin; mhin = mhpo;  mhpo  = t; }
            { float*  t = ppin; ppin = ppout; ppout = t; }
            { __half* t = phin; phin = phpo;  phpo  = t; }
        }
        // final: mel fp32 -> out[:,:,0:256], mel fp16 -> hA; ph fp32 -> ph0, fp16 -> hp0
    }

    // 6. phoneme squared norms + fp16 transpose of ph_enc
    phsq_kernel<<<NB * TPH, 32>>>(ph0, phsq);
    transpose_ph<<<NB * 256, KPAD / 2>>>(hp0, phT);

    // 7. dots (fp16 tensor): logits = 2*dot - ph_sq, masked -> fp32
    {
        dim3 g(MTX, (TPH + 127) / 128, NB);
        attn_mma<0><<<g, 256, SMEMSZA>>>(hA, hp0, phsq, dots, plen, 1, TMEL);
    }

    // 8. softmax -> fp16 probs
    softmax_kernel<<<NB * TMEL, 128>>>(dots, probs);

    // 9. context (fp16 tensor) -> out[:, :, 256:512]
    {
        dim3 g(MTX, 2, NB);
        attn_mma<1><<<g, 256, SMEMSZA>>>(probs, phT, nullptr, out, nullptr, 0, TMEL);
    }
}